// round 4
// baseline (speedup 1.0000x reference)
#include <cuda_runtime.h>

#define N_NODES 10000
#define N_EDGES 160000

// ---------------- scratch (static device globals; no allocation) ----------
static __device__ float g_up_s[N_NODES * 128];   // up_s [n][j]
static __device__ float g_up_v[N_NODES * 384];   // up_v [n][c*128 + j]
static __device__ float g_down[N_NODES * 64];    // down [n][j]
static __device__ float g_m0[N_NODES * 256];     // segment sums mid0
static __device__ float g_m1[N_NODES * 768];     // segment sums mid1 [n][c*256 + i]

#define INV_SQRT_C   0.08838834764831845f   // 1/sqrt(128)
#define INV_SQRT_AUG 0.08574929257125442f   // 1/sqrt(136)
#define SIXTEENTH    0.0625f                // 1/sqrt(256)
#define INV_SQRT3    0.5773502691896258f
#define FINAL_SCALE  0.00390625f            // 1/(sqrt(256)*16)

__device__ __forceinline__ float act_silu(float a, float scale) {
    float y = a * scale;
    return y / (1.0f + __expf(-y));
}

// ---------------- zero scratch ---------------------------------------------
__global__ void zero_kernel() {
    float4 z = make_float4(0.f, 0.f, 0.f, 0.f);
    float4* p0 = (float4*)g_m0;
    float4* p1 = (float4*)g_m1;
    const int n0 = N_NODES * 256 / 4;
    const int n1 = N_NODES * 768 / 4;
    int idx = blockIdx.x * blockDim.x + threadIdx.x;
    int stride = gridDim.x * blockDim.x;
    for (int k = idx; k < n0; k += stride) p0[k] = z;
    for (int k = idx; k < n1; k += stride) p1[k] = z;
}

// ---------------- node pre-pass --------------------------------------------
// Per tile of 32 nodes: s tile (32x128) + v tiles ([c][32][128]) in smem.
// thread map: j = t&127 (output col), g = t>>7; handles nodes g, g+2, ..., g+30.
__device__ __forceinline__ void dual_gemv_128(const float* __restrict__ Xs,
                                              const float* __restrict__ WA,
                                              const float* __restrict__ WB,
                                              int j, int g,
                                              float* accA, float* accB)
{
#pragma unroll
    for (int m = 0; m < 16; m++) { accA[m] = 0.f; accB[m] = 0.f; }
    for (int k = 0; k < 128; k += 4) {
        float a0 = WA[(k + 0) * 128 + j];
        float a1 = WA[(k + 1) * 128 + j];
        float a2 = WA[(k + 2) * 128 + j];
        float a3 = WA[(k + 3) * 128 + j];
        float b0 = WB[(k + 0) * 128 + j];
        float b1 = WB[(k + 1) * 128 + j];
        float b2 = WB[(k + 2) * 128 + j];
        float b3 = WB[(k + 3) * 128 + j];
#pragma unroll
        for (int m = 0; m < 16; m++) {
            float4 x = *(const float4*)(Xs + (g + 2 * m) * 128 + k);
            accA[m] = fmaf(x.x, a0, accA[m]);
            accA[m] = fmaf(x.y, a1, accA[m]);
            accA[m] = fmaf(x.z, a2, accA[m]);
            accA[m] = fmaf(x.w, a3, accA[m]);
            accB[m] = fmaf(x.x, b0, accB[m]);
            accB[m] = fmaf(x.y, b1, accB[m]);
            accB[m] = fmaf(x.z, b2, accB[m]);
            accB[m] = fmaf(x.w, b3, accB[m]);
        }
    }
}

__global__ __launch_bounds__(256, 1) void node_pre_kernel(
    const float* __restrict__ node_feats,
    const float* __restrict__ W_up0, const float* __restrict__ W_up1,
    const float* __restrict__ W_down,
    const float* __restrict__ W_skip0, const float* __restrict__ W_skip1,
    float* __restrict__ out_sc)
{
    extern __shared__ float sm[];
    float* s = sm;              // 32*128
    float* v = sm + 32 * 128;   // 3 planes of 32*128: [c][n][i]
    const int nbase = blockIdx.x * 32;
    const int t = threadIdx.x;

    for (int idx = t; idx < 32 * 512; idx += 256) {
        int nl = idx >> 9;
        int f  = idx & 511;
        int n  = nbase + nl;
        float val = (n < N_NODES) ? node_feats[(size_t)n * 512 + f] : 0.f;
        if (f < 128) {
            s[nl * 128 + f] = val;
        } else {
            int r = f - 128;
            int i = r / 3;
            int c = r - 3 * i;
            v[c * (32 * 128) + nl * 128 + i] = val;
        }
    }
    __syncthreads();

    const int j = t & 127;
    const int g = t >> 7;

    // scalar part: skip (-> sc), up (-> g_up_s)
    {
        float accA[16], accB[16];
        dual_gemv_128(s, W_skip0, W_up0, j, g, accA, accB);
#pragma unroll
        for (int m = 0; m < 16; m++) {
            int n = nbase + g + 2 * m;
            if (n < N_NODES) {
                out_sc[(size_t)n * 512 + j] = accA[m] * INV_SQRT_C;
                g_up_s[n * 128 + j]         = accB[m] * INV_SQRT_C;
            }
        }
    }
    // down projection (N=64): jd = t&63, gd = t>>6, nodes gd + 4m (m<8)
    {
        int jd = t & 63;
        int gd = t >> 6;
        float acc[8];
#pragma unroll
        for (int m = 0; m < 8; m++) acc[m] = 0.f;
        for (int k = 0; k < 128; k += 4) {
            float w0 = W_down[(k + 0) * 64 + jd];
            float w1 = W_down[(k + 1) * 64 + jd];
            float w2 = W_down[(k + 2) * 64 + jd];
            float w3 = W_down[(k + 3) * 64 + jd];
#pragma unroll
            for (int m = 0; m < 8; m++) {
                float4 x = *(const float4*)(s + (gd + 4 * m) * 128 + k);
                acc[m] = fmaf(x.x, w0, acc[m]);
                acc[m] = fmaf(x.y, w1, acc[m]);
                acc[m] = fmaf(x.z, w2, acc[m]);
                acc[m] = fmaf(x.w, w3, acc[m]);
            }
        }
#pragma unroll
        for (int m = 0; m < 8; m++) {
            int n = nbase + gd + 4 * m;
            if (n < N_NODES) g_down[n * 64 + jd] = acc[m] * INV_SQRT_C;
        }
    }
    // vector part: 3 channels, skip (-> sc) and up (-> g_up_v)
    for (int c = 0; c < 3; c++) {
        const float* vp = v + c * (32 * 128);
        float accA[16], accB[16];
        dual_gemv_128(vp, W_skip1, W_up1, j, g, accA, accB);
#pragma unroll
        for (int m = 0; m < 16; m++) {
            int n = nbase + g + 2 * m;
            if (n < N_NODES) {
                out_sc[(size_t)n * 512 + 128 + j * 3 + c] = accA[m] * INV_SQRT_C;
                g_up_v[n * 384 + c * 128 + j]             = accB[m] * INV_SQRT_C;
            }
        }
    }
}

// ---------------- edge MLP + tensor product + scatter ----------------------
// CTA = 64 edges, 256 threads.
// GEMM thread map: colgroup = t&63 (4 cols), edgegroup = t>>6 (16 edges).
template <int K, int LDX, bool DOSILU>
__device__ __forceinline__ void mlp_layer(const float* __restrict__ X,
                                          const float* __restrict__ W,
                                          float* __restrict__ Y,
                                          float scale)
{
    const int t  = threadIdx.x;
    const int j0 = (t & 63) * 4;
    const int e0 = (t >> 6) * 16;
    float acc[16][4];
#pragma unroll
    for (int m = 0; m < 16; m++) {
        acc[m][0] = 0.f; acc[m][1] = 0.f; acc[m][2] = 0.f; acc[m][3] = 0.f;
    }
    const float* xb = X + e0 * LDX;
    for (int k = 0; k < K; k += 4) {
        float4 w0 = *(const float4*)(W + (k + 0) * 256 + j0);
        float4 w1 = *(const float4*)(W + (k + 1) * 256 + j0);
        float4 w2 = *(const float4*)(W + (k + 2) * 256 + j0);
        float4 w3 = *(const float4*)(W + (k + 3) * 256 + j0);
#pragma unroll
        for (int m = 0; m < 16; m++) {
            float4 x = *(const float4*)(xb + m * LDX + k);
            acc[m][0] = fmaf(x.x, w0.x, acc[m][0]);
            acc[m][1] = fmaf(x.x, w0.y, acc[m][1]);
            acc[m][2] = fmaf(x.x, w0.z, acc[m][2]);
            acc[m][3] = fmaf(x.x, w0.w, acc[m][3]);
            acc[m][0] = fmaf(x.y, w1.x, acc[m][0]);
            acc[m][1] = fmaf(x.y, w1.y, acc[m][1]);
            acc[m][2] = fmaf(x.y, w1.z, acc[m][2]);
            acc[m][3] = fmaf(x.y, w1.w, acc[m][3]);
            acc[m][0] = fmaf(x.z, w2.x, acc[m][0]);
            acc[m][1] = fmaf(x.z, w2.y, acc[m][1]);
            acc[m][2] = fmaf(x.z, w2.z, acc[m][2]);
            acc[m][3] = fmaf(x.z, w2.w, acc[m][3]);
            acc[m][0] = fmaf(x.w, w3.x, acc[m][0]);
            acc[m][1] = fmaf(x.w, w3.y, acc[m][1]);
            acc[m][2] = fmaf(x.w, w3.z, acc[m][2]);
            acc[m][3] = fmaf(x.w, w3.w, acc[m][3]);
        }
    }
#pragma unroll
    for (int m = 0; m < 16; m++) {
        float4 r;
        if (DOSILU) {
            r.x = act_silu(acc[m][0], scale);
            r.y = act_silu(acc[m][1], scale);
            r.z = act_silu(acc[m][2], scale);
            r.w = act_silu(acc[m][3], scale);
        } else {
            r.x = acc[m][0] * scale; r.y = acc[m][1] * scale;
            r.z = acc[m][2] * scale; r.w = acc[m][3] * scale;
        }
        *(float4*)(Y + (e0 + m) * 256 + j0) = r;
    }
}

// Layer 3 (N=512) fused with the tensor product + atomic scatter.
// Thread map per pass (32 edges): j = t&127, eg = t>>7 -> 16 edges each.
// Each thread accumulates columns {j, 128+j, 256+j, 384+j} = w1..w4.
__device__ __forceinline__ void final_layer_tp(const float* __restrict__ H,
                                               const float* __restrict__ Wm3,
                                               const int* __restrict__ sidx,
                                               const int* __restrict__ ridx,
                                               const float* __restrict__ eattr)
{
    const int t  = threadIdx.x;
    const int j  = t & 127;
    const int eg = t >> 7;
#pragma unroll 1
    for (int p = 0; p < 2; p++) {
        const int e0 = p * 32 + eg * 16;
        float a1[16], a2[16], a3[16], a4[16];
#pragma unroll
        for (int m = 0; m < 16; m++) { a1[m] = 0.f; a2[m] = 0.f; a3[m] = 0.f; a4[m] = 0.f; }
        const float* xb = H + e0 * 256;
        for (int k = 0; k < 256; k += 4) {
            float w1k[4], w2k[4], w3k[4], w4k[4];
#pragma unroll
            for (int q = 0; q < 4; q++) {
                const float* wr = Wm3 + (size_t)(k + q) * 512;
                w1k[q] = wr[j];
                w2k[q] = wr[128 + j];
                w3k[q] = wr[256 + j];
                w4k[q] = wr[384 + j];
            }
#pragma unroll
            for (int m = 0; m < 16; m++) {
                float4 x = *(const float4*)(xb + m * 256 + k);
                a1[m] = fmaf(x.x, w1k[0], a1[m]);
                a1[m] = fmaf(x.y, w1k[1], a1[m]);
                a1[m] = fmaf(x.z, w1k[2], a1[m]);
                a1[m] = fmaf(x.w, w1k[3], a1[m]);
                a2[m] = fmaf(x.x, w2k[0], a2[m]);
                a2[m] = fmaf(x.y, w2k[1], a2[m]);
                a2[m] = fmaf(x.z, w2k[2], a2[m]);
                a2[m] = fmaf(x.w, w2k[3], a2[m]);
                a3[m] = fmaf(x.x, w3k[0], a3[m]);
                a3[m] = fmaf(x.y, w3k[1], a3[m]);
                a3[m] = fmaf(x.z, w3k[2], a3[m]);
                a3[m] = fmaf(x.w, w3k[3], a3[m]);
                a4[m] = fmaf(x.x, w4k[0], a4[m]);
                a4[m] = fmaf(x.y, w4k[1], a4[m]);
                a4[m] = fmaf(x.z, w4k[2], a4[m]);
                a4[m] = fmaf(x.w, w4k[3], a4[m]);
            }
        }
#pragma unroll 1
        for (int m = 0; m < 16; m++) {
            int e   = e0 + m;
            int snd = sidx[e];
            int rcv = ridx[e];
            float xs  = g_up_s[snd * 128 + j];
            float xv0 = g_up_v[snd * 384 + j];
            float xv1 = g_up_v[snd * 384 + 128 + j];
            float xv2 = g_up_v[snd * 384 + 256 + j];
            float y0  = eattr[e * 4 + 0];
            float yv0 = eattr[e * 4 + 1];
            float yv1 = eattr[e * 4 + 2];
            float yv2 = eattr[e * 4 + 3];
            float w1 = a1[m] * SIXTEENTH;
            float w2 = a2[m] * SIXTEENTH;
            float w3 = a3[m] * SIXTEENTH;
            float w4 = a4[m] * SIXTEENTH;

            float out0a = w1 * xs * y0;
            float dotxy = xv0 * yv0 + xv1 * yv1 + xv2 * yv2;
            float out0b = w4 * dotxy * INV_SQRT3;
            float* m0r = g_m0 + (size_t)rcv * 256;
            atomicAdd(m0r + j, out0a);
            atomicAdd(m0r + 128 + j, out0b);

            float w2xs = w2 * xs;
            float w3y0 = w3 * y0;
            float* m1r = g_m1 + (size_t)rcv * 768;
            atomicAdd(m1r +   0 + j, w2xs * yv0);
            atomicAdd(m1r + 256 + j, w2xs * yv1);
            atomicAdd(m1r + 512 + j, w2xs * yv2);
            atomicAdd(m1r + 128 + j, w3y0 * xv0);
            atomicAdd(m1r + 384 + j, w3y0 * xv1);
            atomicAdd(m1r + 640 + j, w3y0 * xv2);
        }
    }
}

#define EDGE_SMEM_BYTES ((64 * 136 + 2 * 64 * 256) * 4 + 128 * 4 + 64 * 4 * 4)

__global__ __launch_bounds__(256, 1) void edge_kernel(
    const float* __restrict__ edge_attrs,
    const float* __restrict__ edge_feats,
    const int* __restrict__ edge_index,
    const float* __restrict__ Wm0, const float* __restrict__ Wm1,
    const float* __restrict__ Wm2, const float* __restrict__ Wm3)
{
    extern __shared__ float sm[];
    float* aug = sm;                       // 64*136
    float* h0  = aug + 64 * 136;           // 64*256
    float* h1  = h0 + 64 * 256;            // 64*256
    int*   sidx = (int*)(h1 + 64 * 256);   // 64
    int*   ridx = sidx + 64;               // 64
    float* eattr = (float*)(ridx + 64);    // 64*4

    const int t = threadIdx.x;
    const int ebase = blockIdx.x * 64;

    if (t < 64) {
        sidx[t] = edge_index[(size_t)(ebase + t) * 2];
        ridx[t] = edge_index[(size_t)(ebase + t) * 2 + 1];
    }
    if (t >= 64 && t < 64 + 256) {
        // nothing; eattr loaded below by all threads
    }
    for (int idx = t; idx < 64 * 4; idx += 256)
        eattr[idx] = edge_attrs[(size_t)ebase * 4 + idx];
    __syncthreads();

    // build aug = [edge_feats(8) | down[sender](64) | down[receiver](64)]
    for (int idx = t; idx < 64 * 136; idx += 256) {
        int e = idx / 136;
        int f = idx - e * 136;
        float val;
        if (f < 8)       val = edge_feats[(size_t)(ebase + e) * 8 + f];
        else if (f < 72) val = g_down[sidx[e] * 64 + (f - 8)];
        else             val = g_down[ridx[e] * 64 + (f - 72)];
        aug[idx] = val;
    }
    __syncthreads();

    mlp_layer<136, 136, true>(aug, Wm0, h0, INV_SQRT_AUG);
    __syncthreads();
    mlp_layer<256, 256, true>(h0, Wm1, h1, SIXTEENTH);
    __syncthreads();
    mlp_layer<256, 256, true>(h1, Wm2, h0, SIXTEENTH);
    __syncthreads();
    final_layer_tp(h0, Wm3, sidx, ridx, eattr);
}

// ---------------- node post-pass --------------------------------------------
__global__ __launch_bounds__(256, 1) void node_post_kernel(
    const float* __restrict__ W_lin0,
    const float* __restrict__ W_lin1,
    float* __restrict__ out)
{
    __shared__ float tile[32 * 256];
    const int nbase = blockIdx.x * 32;
    const int t = threadIdx.x;
    const int j = t & 127;
    const int g = t >> 7;

    // msg_s = m0 @ W_lin0 * FINAL_SCALE
    for (int idx = t; idx < 32 * 256; idx += 256) {
        int nl = idx >> 8;
        int k  = idx & 255;
        int n  = nbase + nl;
        tile[idx] = (n < N_NODES) ? g_m0[(size_t)n * 256 + k] : 0.f;
    }
    __syncthreads();
    {
        float acc[16];
#pragma unroll
        for (int m = 0; m < 16; m++) acc[m] = 0.f;
        for (int k = 0; k < 256; k += 4) {
            float w0 = W_lin0[(k + 0) * 128 + j];
            float w1 = W_lin0[(k + 1) * 128 + j];
            float w2 = W_lin0[(k + 2) * 128 + j];
            float w3 = W_lin0[(k + 3) * 128 + j];
#pragma unroll
            for (int m = 0; m < 16; m++) {
                float4 x = *(const float4*)(tile + (g + 2 * m) * 256 + k);
                acc[m] = fmaf(x.x, w0, acc[m]);
                acc[m] = fmaf(x.y, w1, acc[m]);
                acc[m] = fmaf(x.z, w2, acc[m]);
                acc[m] = fmaf(x.w, w3, acc[m]);
            }
        }
#pragma unroll
        for (int m = 0; m < 16; m++) {
            int n = nbase + g + 2 * m;
            if (n < N_NODES) out[(size_t)n * 512 + j * 4 + 0] = acc[m] * FINAL_SCALE;
        }
    }
    // msg_v channels
    for (int c = 0; c < 3; c++) {
        __syncthreads();
        for (int idx = t; idx < 32 * 256; idx += 256) {
            int nl = idx >> 8;
            int k  = idx & 255;
            int n  = nbase + nl;
            tile[idx] = (n < N_NODES) ? g_m1[(size_t)n * 768 + c * 256 + k] : 0.f;
        }
        __syncthreads();
        float acc[16];
#pragma unroll
        for (int m = 0; m < 16; m++) acc[m] = 0.f;
        for (int k = 0; k < 256; k += 4) {
            float w0 = W_lin1[(k + 0) * 128 + j];
            float w1 = W_lin1[(k + 1) * 128 + j];
            float w2 = W_lin1[(k + 2) * 128 + j];
            float w3 = W_lin1[(k + 3) * 128 + j];
#pragma unroll
            for (int m = 0; m < 16; m++) {
                float4 x = *(const float4*)(tile + (g + 2 * m) * 256 + k);
                acc[m] = fmaf(x.x, w0, acc[m]);
                acc[m] = fmaf(x.y, w1, acc[m]);
                acc[m] = fmaf(x.z, w2, acc[m]);
                acc[m] = fmaf(x.w, w3, acc[m]);
            }
        }
#pragma unroll
        for (int m = 0; m < 16; m++) {
            int n = nbase + g + 2 * m;
            if (n < N_NODES) out[(size_t)n * 512 + j * 4 + 1 + c] = acc[m] * FINAL_SCALE;
        }
    }
}

// ---------------- launch -----------------------------------------------------
extern "C" void kernel_launch(void* const* d_in, const int* in_sizes, int n_in,
                              void* d_out, int out_size)
{
    (void)in_sizes; (void)n_in; (void)out_size;
    const float* node_feats = (const float*)d_in[1];
    const float* edge_attrs = (const float*)d_in[2];
    const float* edge_feats = (const float*)d_in[3];
    const int*   edge_index = (const int*)d_in[4];
    const float* W_up0   = (const float*)d_in[5];
    const float* W_up1   = (const float*)d_in[6];
    const float* W_down  = (const float*)d_in[7];
    const float* Wm0     = (const float*)d_in[8];
    const float* Wm1     = (const float*)d_in[9];
    const float* Wm2     = (const float*)d_in[10];
    const float* Wm3     = (const float*)d_in[11];
    const float* W_lin0  = (const float*)d_in[12];
    const float* W_lin1  = (const float*)d_in[13];
    const float* W_skip0 = (const float*)d_in[14];
    const float* W_skip1 = (const float*)d_in[15];

    float* out    = (float*)d_out;                          // (N,128,4)
    float* out_sc = out + (size_t)N_NODES * 512;            // (N,512)

    cudaFuncSetAttribute(node_pre_kernel,
                         cudaFuncAttributeMaxDynamicSharedMemorySize, 64 * 1024);
    cudaFuncSetAttribute(edge_kernel,
                         cudaFuncAttributeMaxDynamicSharedMemorySize, EDGE_SMEM_BYTES);

    zero_kernel<<<512, 256>>>();
    node_pre_kernel<<<(N_NODES + 31) / 32, 256, 64 * 1024>>>(
        node_feats, W_up0, W_up1, W_down, W_skip0, W_skip1, out_sc);
    edge_kernel<<<N_EDGES / 64, 256, EDGE_SMEM_BYTES>>>(
        edge_attrs, edge_feats, edge_index, Wm0, Wm1, Wm2, Wm3);
    node_post_kernel<<<(N_NODES + 31) / 32, 256>>>(W_lin0, W_lin1, out);
}

// round 7
// speedup vs baseline: 1.0391x; 1.0391x over previous
#include <cuda_runtime.h>

#define N_NODES 10000
#define N_EDGES 160000

// ---------------- scratch (static device globals; no allocation) ----------
static __device__ float g_up_s[N_NODES * 128];   // up_s [n][j]
static __device__ float g_up_v[N_NODES * 384];   // up_v [n][c*128 + j]
static __device__ float g_down[N_NODES * 64];    // down [n][j]
static __device__ float g_m0[N_NODES * 256];     // segment sums mid0
static __device__ float g_m1[N_NODES * 768];     // segment sums mid1 [n][c*256 + i]

#define INV_SQRT_C   0.08838834764831845f   // 1/sqrt(128)
#define INV_SQRT_AUG 0.08574929257125442f   // 1/sqrt(136)
#define SIXTEENTH    0.0625f                // 1/sqrt(256)
#define INV_SQRT3    0.5773502691896258f
#define FINAL_SCALE  0.00390625f            // 1/(sqrt(256)*16)

typedef unsigned long long ull;

__device__ __forceinline__ float act_silu(float a, float scale) {
    float y = a * scale;
    return y / (1.0f + __expf(-y));
}

// ---- packed f32x2 helpers (FFMA2: 2x fp32 throughput, exact fp32) --------
__device__ __forceinline__ ull bcast2(float x) {
    ull r; asm("mov.b64 %0, {%1, %1};" : "=l"(r) : "f"(x)); return r;
}
__device__ __forceinline__ ull ffma2(ull a, ull b, ull c) {
    ull d; asm("fma.rn.f32x2 %0, %1, %2, %3;" : "=l"(d) : "l"(a), "l"(b), "l"(c));
    return d;
}
__device__ __forceinline__ float2 unpack2(ull v) {
    float2 f; asm("mov.b64 {%0, %1}, %2;" : "=f"(f.x), "=f"(f.y) : "l"(v));
    return f;
}

// ---------------- zero scratch ---------------------------------------------
__global__ void zero_kernel() {
    float4 z = make_float4(0.f, 0.f, 0.f, 0.f);
    float4* p0 = (float4*)g_m0;
    float4* p1 = (float4*)g_m1;
    const int n0 = N_NODES * 256 / 4;
    const int n1 = N_NODES * 768 / 4;
    int idx = blockIdx.x * blockDim.x + threadIdx.x;
    int stride = gridDim.x * blockDim.x;
    for (int k = idx; k < n0; k += stride) p0[k] = z;
    for (int k = idx; k < n1; k += stride) p1[k] = z;
}

// ---------------- node pre-pass --------------------------------------------
__device__ __forceinline__ void dual_gemv_128(const float* __restrict__ Xs,
                                              const float* __restrict__ WA,
                                              const float* __restrict__ WB,
                                              int j, int g,
                                              float* accA, float* accB)
{
#pragma unroll
    for (int m = 0; m < 16; m++) { accA[m] = 0.f; accB[m] = 0.f; }
    for (int k = 0; k < 128; k += 4) {
        float a0 = WA[(k + 0) * 128 + j];
        float a1 = WA[(k + 1) * 128 + j];
        float a2 = WA[(k + 2) * 128 + j];
        float a3 = WA[(k + 3) * 128 + j];
        float b0 = WB[(k + 0) * 128 + j];
        float b1 = WB[(k + 1) * 128 + j];
        float b2 = WB[(k + 2) * 128 + j];
        float b3 = WB[(k + 3) * 128 + j];
#pragma unroll
        for (int m = 0; m < 16; m++) {
            float4 x = *(const float4*)(Xs + (g + 2 * m) * 128 + k);
            accA[m] = fmaf(x.x, a0, accA[m]);
            accA[m] = fmaf(x.y, a1, accA[m]);
            accA[m] = fmaf(x.z, a2, accA[m]);
            accA[m] = fmaf(x.w, a3, accA[m]);
            accB[m] = fmaf(x.x, b0, accB[m]);
            accB[m] = fmaf(x.y, b1, accB[m]);
            accB[m] = fmaf(x.z, b2, accB[m]);
            accB[m] = fmaf(x.w, b3, accB[m]);
        }
    }
}

__global__ __launch_bounds__(256, 1) void node_pre_kernel(
    const float* __restrict__ node_feats,
    const float* __restrict__ W_up0, const float* __restrict__ W_up1,
    const float* __restrict__ W_down,
    const float* __restrict__ W_skip0, const float* __restrict__ W_skip1,
    float* __restrict__ out_sc)
{
    extern __shared__ float sm[];
    float* s = sm;              // 32*128
    float* v = sm + 32 * 128;   // 3 planes of 32*128: [c][n][i]
    const int nbase = blockIdx.x * 32;
    const int t = threadIdx.x;

    for (int idx = t; idx < 32 * 512; idx += 256) {
        int nl = idx >> 9;
        int f  = idx & 511;
        int n  = nbase + nl;
        float val = (n < N_NODES) ? node_feats[(size_t)n * 512 + f] : 0.f;
        if (f < 128) {
            s[nl * 128 + f] = val;
        } else {
            int r = f - 128;
            int i = r / 3;
            int c = r - 3 * i;
            v[c * (32 * 128) + nl * 128 + i] = val;
        }
    }
    __syncthreads();

    const int j = t & 127;
    const int g = t >> 7;

    {
        float accA[16], accB[16];
        dual_gemv_128(s, W_skip0, W_up0, j, g, accA, accB);
#pragma unroll
        for (int m = 0; m < 16; m++) {
            int n = nbase + g + 2 * m;
            if (n < N_NODES) {
                out_sc[(size_t)n * 512 + j] = accA[m] * INV_SQRT_C;
                g_up_s[n * 128 + j]         = accB[m] * INV_SQRT_C;
            }
        }
    }
    {
        int jd = t & 63;
        int gd = t >> 6;
        float acc[8];
#pragma unroll
        for (int m = 0; m < 8; m++) acc[m] = 0.f;
        for (int k = 0; k < 128; k += 4) {
            float w0 = W_down[(k + 0) * 64 + jd];
            float w1 = W_down[(k + 1) * 64 + jd];
            float w2 = W_down[(k + 2) * 64 + jd];
            float w3 = W_down[(k + 3) * 64 + jd];
#pragma unroll
            for (int m = 0; m < 8; m++) {
                float4 x = *(const float4*)(s + (gd + 4 * m) * 128 + k);
                acc[m] = fmaf(x.x, w0, acc[m]);
                acc[m] = fmaf(x.y, w1, acc[m]);
                acc[m] = fmaf(x.z, w2, acc[m]);
                acc[m] = fmaf(x.w, w3, acc[m]);
            }
        }
#pragma unroll
        for (int m = 0; m < 8; m++) {
            int n = nbase + gd + 4 * m;
            if (n < N_NODES) g_down[n * 64 + jd] = acc[m] * INV_SQRT_C;
        }
    }
    for (int c = 0; c < 3; c++) {
        const float* vp = v + c * (32 * 128);
        float accA[16], accB[16];
        dual_gemv_128(vp, W_skip1, W_up1, j, g, accA, accB);
#pragma unroll
        for (int m = 0; m < 16; m++) {
            int n = nbase + g + 2 * m;
            if (n < N_NODES) {
                out_sc[(size_t)n * 512 + 128 + j * 3 + c] = accA[m] * INV_SQRT_C;
                g_up_v[n * 384 + c * 128 + j]             = accB[m] * INV_SQRT_C;
            }
        }
    }
}

// ---------------- edge MLP (packed f32x2) -----------------------------------
// Activation smem layout (per 16-edge group g, pairing edges (i, i+8)):
//   X[g*16*K + i*2*K + 2*k + p]  ,  i in [0,8), p in {0,1}
// One ulonglong2 (LDS.128) at (g,i,2k) = packed f32x2 pairs for rows k, k+1.
template <int K>
__device__ __forceinline__ void mlp_layer2(const float* __restrict__ X,
                                           const float* __restrict__ W,
                                           float* __restrict__ Y,
                                           float scale)
{
    const int t  = threadIdx.x;
    const int j0 = (t & 63) * 4;
    const int g  = t >> 6;
    ull acc[8][4];
#pragma unroll
    for (int i = 0; i < 8; i++) {
#pragma unroll
        for (int c = 0; c < 4; c++) acc[i][c] = 0ULL;
    }
    const float* xb = X + g * 16 * K;
#pragma unroll 2
    for (int k = 0; k < K; k += 2) {
        float4 wa = *(const float4*)(W + (size_t)(k + 0) * 256 + j0);
        float4 wb = *(const float4*)(W + (size_t)(k + 1) * 256 + j0);
        ull wa0 = bcast2(wa.x), wa1 = bcast2(wa.y), wa2 = bcast2(wa.z), wa3 = bcast2(wa.w);
        ull wb0 = bcast2(wb.x), wb1 = bcast2(wb.y), wb2 = bcast2(wb.z), wb3 = bcast2(wb.w);
#pragma unroll
        for (int i = 0; i < 8; i++) {
            ulonglong2 xv = *(const ulonglong2*)(xb + i * 2 * K + 2 * k);
            acc[i][0] = ffma2(xv.x, wa0, acc[i][0]);
            acc[i][1] = ffma2(xv.x, wa1, acc[i][1]);
            acc[i][2] = ffma2(xv.x, wa2, acc[i][2]);
            acc[i][3] = ffma2(xv.x, wa3, acc[i][3]);
            acc[i][0] = ffma2(xv.y, wb0, acc[i][0]);
            acc[i][1] = ffma2(xv.y, wb1, acc[i][1]);
            acc[i][2] = ffma2(xv.y, wb2, acc[i][2]);
            acc[i][3] = ffma2(xv.y, wb3, acc[i][3]);
        }
    }
    // silu + write back in packed layout (K_out = 256); the thread's 8 floats
    // per pair are contiguous: [2*j0 .. 2*j0+7] -> two STS.128.
    float* yb = Y + g * 16 * 256;
#pragma unroll
    for (int i = 0; i < 8; i++) {
        float2 v0 = unpack2(acc[i][0]);
        float2 v1 = unpack2(acc[i][1]);
        float2 v2 = unpack2(acc[i][2]);
        float2 v3 = unpack2(acc[i][3]);
        float4 o0, o1;
        o0.x = act_silu(v0.x, scale); o0.y = act_silu(v0.y, scale);
        o0.z = act_silu(v1.x, scale); o0.w = act_silu(v1.y, scale);
        o1.x = act_silu(v2.x, scale); o1.y = act_silu(v2.y, scale);
        o1.z = act_silu(v3.x, scale); o1.w = act_silu(v3.y, scale);
        *(float4*)(yb + i * 512 + 2 * j0)     = o0;
        *(float4*)(yb + i * 512 + 2 * j0 + 4) = o1;
    }
}

// Layer 3 (N=512) fused with tensor product + atomic scatter, f32x2 version.
// Per pass: 32 edges (2 groups of 16), thread map j = t&127, eg = t>>7.
__device__ __forceinline__ void final_layer_tp2(const float* __restrict__ H,
                                                const float* __restrict__ Wm3,
                                                const int* __restrict__ sidx,
                                                const int* __restrict__ ridx,
                                                const float* __restrict__ eattr)
{
    const int t  = threadIdx.x;
    const int j  = t & 127;
    const int eg = t >> 7;
#pragma unroll 1
    for (int p = 0; p < 2; p++) {
        const int e0 = p * 32 + eg * 16;
        const int gq = e0 >> 4;
        ull a1[8], a2[8], a3[8], a4[8];
#pragma unroll
        for (int i = 0; i < 8; i++) { a1[i] = 0ULL; a2[i] = 0ULL; a3[i] = 0ULL; a4[i] = 0ULL; }
        const float* xb = H + gq * 16 * 256;
#pragma unroll 2
        for (int k = 0; k < 256; k += 2) {
            const float* wr0 = Wm3 + (size_t)k * 512;
            const float* wr1 = wr0 + 512;
            ull w1a = bcast2(wr0[j]),       w1b = bcast2(wr1[j]);
            ull w2a = bcast2(wr0[128 + j]), w2b = bcast2(wr1[128 + j]);
            ull w3a = bcast2(wr0[256 + j]), w3b = bcast2(wr1[256 + j]);
            ull w4a = bcast2(wr0[384 + j]), w4b = bcast2(wr1[384 + j]);
#pragma unroll
            for (int i = 0; i < 8; i++) {
                ulonglong2 xv = *(const ulonglong2*)(xb + i * 512 + 2 * k);
                a1[i] = ffma2(xv.x, w1a, a1[i]);
                a2[i] = ffma2(xv.x, w2a, a2[i]);
                a3[i] = ffma2(xv.x, w3a, a3[i]);
                a4[i] = ffma2(xv.x, w4a, a4[i]);
                a1[i] = ffma2(xv.y, w1b, a1[i]);
                a2[i] = ffma2(xv.y, w2b, a2[i]);
                a3[i] = ffma2(xv.y, w3b, a3[i]);
                a4[i] = ffma2(xv.y, w4b, a4[i]);
            }
        }
#pragma unroll 1
        for (int i = 0; i < 8; i++) {
            float2 w1v = unpack2(a1[i]);
            float2 w2v = unpack2(a2[i]);
            float2 w3v = unpack2(a3[i]);
            float2 w4v = unpack2(a4[i]);
#pragma unroll 1
            for (int pp = 0; pp < 2; pp++) {
                int e   = e0 + i + pp * 8;
                int snd = sidx[e];
                int rcv = ridx[e];
                float xs  = g_up_s[snd * 128 + j];
                float xv0 = g_up_v[snd * 384 + j];
                float xv1 = g_up_v[snd * 384 + 128 + j];
                float xv2 = g_up_v[snd * 384 + 256 + j];
                float y0  = eattr[e * 4 + 0];
                float yv0 = eattr[e * 4 + 1];
                float yv1 = eattr[e * 4 + 2];
                float yv2 = eattr[e * 4 + 3];
                float w1 = (pp ? w1v.y : w1v.x) * SIXTEENTH;
                float w2 = (pp ? w2v.y : w2v.x) * SIXTEENTH;
                float w3 = (pp ? w3v.y : w3v.x) * SIXTEENTH;
                float w4 = (pp ? w4v.y : w4v.x) * SIXTEENTH;

                float out0a = w1 * xs * y0;
                float dotxy = xv0 * yv0 + xv1 * yv1 + xv2 * yv2;
                float out0b = w4 * dotxy * INV_SQRT3;
                float* m0r = g_m0 + (size_t)rcv * 256;
                atomicAdd(m0r + j, out0a);
                atomicAdd(m0r + 128 + j, out0b);

                float w2xs = w2 * xs;
                float w3y0 = w3 * y0;
                float* m1r = g_m1 + (size_t)rcv * 768;
                atomicAdd(m1r +   0 + j, w2xs * yv0);
                atomicAdd(m1r + 256 + j, w2xs * yv1);
                atomicAdd(m1r + 512 + j, w2xs * yv2);
                atomicAdd(m1r + 128 + j, w3y0 * xv0);
                atomicAdd(m1r + 384 + j, w3y0 * xv1);
                atomicAdd(m1r + 640 + j, w3y0 * xv2);
            }
        }
    }
}

#define EDGE_SMEM_BYTES ((64 * 136 + 2 * 64 * 256) * 4 + 128 * 4 + 64 * 4 * 4)

__global__ __launch_bounds__(256, 1) void edge_kernel(
    const float* __restrict__ edge_attrs,
    const float* __restrict__ edge_feats,
    const int* __restrict__ edge_index,
    const float* __restrict__ Wm0, const float* __restrict__ Wm1,
    const float* __restrict__ Wm2, const float* __restrict__ Wm3)
{
    extern __shared__ float sm[];
    float* aug = sm;                       // 64*136  (packed pair layout)
    float* h0  = aug + 64 * 136;           // 64*256  (packed)
    float* h1  = h0 + 64 * 256;            // 64*256  (packed)
    int*   sidx = (int*)(h1 + 64 * 256);   // 64
    int*   ridx = sidx + 64;               // 64
    float* eattr = (float*)(ridx + 64);    // 64*4

    const int t = threadIdx.x;
    const int ebase = blockIdx.x * 64;

    if (t < 64) {
        sidx[t] = edge_index[(size_t)(ebase + t) * 2];
        ridx[t] = edge_index[(size_t)(ebase + t) * 2 + 1];
    }
    for (int idx = t; idx < 64 * 4; idx += 256)
        eattr[idx] = edge_attrs[(size_t)ebase * 4 + idx];
    __syncthreads();

    // build aug = [edge_feats(8) | down[sender](64) | down[receiver](64)]
    // written directly in packed pair layout: addr(e,f) with e = g*16 + i + 8p
    for (int idx = t; idx < 64 * 136; idx += 256) {
        int e = idx / 136;
        int f = idx - e * 136;
        float val;
        if (f < 8)       val = edge_feats[(size_t)(ebase + e) * 8 + f];
        else if (f < 72) val = g_down[sidx[e] * 64 + (f - 8)];
        else             val = g_down[ridx[e] * 64 + (f - 72)];
        int g2 = e >> 4;
        int r  = e & 15;
        int i  = r & 7;
        int pp = r >> 3;
        aug[g2 * (16 * 136) + i * 272 + 2 * f + pp] = val;
    }
    __syncthreads();

    mlp_layer2<136>(aug, Wm0, h0, INV_SQRT_AUG);
    __syncthreads();
    mlp_layer2<256>(h0, Wm1, h1, SIXTEENTH);
    __syncthreads();
    mlp_layer2<256>(h1, Wm2, h0, SIXTEENTH);
    __syncthreads();
    final_layer_tp2(h0, Wm3, sidx, ridx, eattr);
}

// ---------------- node post-pass --------------------------------------------
__global__ __launch_bounds__(256, 2) void node_post_kernel(
    const float* __restrict__ W_lin0,
    const float* __restrict__ W_lin1,
    float* __restrict__ out)
{
    __shared__ float tile[32 * 256];
    const int nbase = blockIdx.x * 32;
    const int t = threadIdx.x;
    const int j = t & 127;
    const int g = t >> 7;

    for (int idx = t; idx < 32 * 256; idx += 256) {
        int nl = idx >> 8;
        int k  = idx & 255;
        int n  = nbase + nl;
        tile[idx] = (n < N_NODES) ? g_m0[(size_t)n * 256 + k] : 0.f;
    }
    __syncthreads();
    {
        float acc[16];
#pragma unroll
        for (int m = 0; m < 16; m++) acc[m] = 0.f;
        for (int k = 0; k < 256; k += 4) {
            float w0 = W_lin0[(k + 0) * 128 + j];
            float w1 = W_lin0[(k + 1) * 128 + j];
            float w2 = W_lin0[(k + 2) * 128 + j];
            float w3 = W_lin0[(k + 3) * 128 + j];
#pragma unroll
            for (int m = 0; m < 16; m++) {
                float4 x = *(const float4*)(tile + (g + 2 * m) * 256 + k);
                acc[m] = fmaf(x.x, w0, acc[m]);
                acc[m] = fmaf(x.y, w1, acc[m]);
                acc[m] = fmaf(x.z, w2, acc[m]);
                acc[m] = fmaf(x.w, w3, acc[m]);
            }
        }
#pragma unroll
        for (int m = 0; m < 16; m++) {
            int n = nbase + g + 2 * m;
            if (n < N_NODES) out[(size_t)n * 512 + j * 4 + 0] = acc[m] * FINAL_SCALE;
        }
    }
    for (int c = 0; c < 3; c++) {
        __syncthreads();
        for (int idx = t; idx < 32 * 256; idx += 256) {
            int nl = idx >> 8;
            int k  = idx & 255;
            int n  = nbase + nl;
            tile[idx] = (n < N_NODES) ? g_m1[(size_t)n * 768 + c * 256 + k] : 0.f;
        }
        __syncthreads();
        float acc[16];
#pragma unroll
        for (int m = 0; m < 16; m++) acc[m] = 0.f;
        for (int k = 0; k < 256; k += 4) {
            float w0 = W_lin1[(k + 0) * 128 + j];
            float w1 = W_lin1[(k + 1) * 128 + j];
            float w2 = W_lin1[(k + 2) * 128 + j];
            float w3 = W_lin1[(k + 3) * 128 + j];
#pragma unroll
            for (int m = 0; m < 16; m++) {
                float4 x = *(const float4*)(tile + (g + 2 * m) * 256 + k);
                acc[m] = fmaf(x.x, w0, acc[m]);
                acc[m] = fmaf(x.y, w1, acc[m]);
                acc[m] = fmaf(x.z, w2, acc[m]);
                acc[m] = fmaf(x.w, w3, acc[m]);
            }
        }
#pragma unroll
        for (int m = 0; m < 16; m++) {
            int n = nbase + g + 2 * m;
            if (n < N_NODES) out[(size_t)n * 512 + j * 4 + 1 + c] = acc[m] * FINAL_SCALE;
        }
    }
}

// ---------------- launch -----------------------------------------------------
extern "C" void kernel_launch(void* const* d_in, const int* in_sizes, int n_in,
                              void* d_out, int out_size)
{
    (void)in_sizes; (void)n_in; (void)out_size;
    const float* node_feats = (const float*)d_in[1];
    const float* edge_attrs = (const float*)d_in[2];
    const float* edge_feats = (const float*)d_in[3];
    const int*   edge_index = (const int*)d_in[4];
    const float* W_up0   = (const float*)d_in[5];
    const float* W_up1   = (const float*)d_in[6];
    const float* W_down  = (const float*)d_in[7];
    const float* Wm0     = (const float*)d_in[8];
    const float* Wm1     = (const float*)d_in[9];
    const float* Wm2     = (const float*)d_in[10];
    const float* Wm3     = (const float*)d_in[11];
    const float* W_lin0  = (const float*)d_in[12];
    const float* W_lin1  = (const float*)d_in[13];
    const float* W_skip0 = (const float*)d_in[14];
    const float* W_skip1 = (const float*)d_in[15];

    float* out    = (float*)d_out;                          // (N,128,4)
    float* out_sc = out + (size_t)N_NODES * 512;            // (N,512)

    cudaFuncSetAttribute(node_pre_kernel,
                         cudaFuncAttributeMaxDynamicSharedMemorySize, 64 * 1024);
    cudaFuncSetAttribute(edge_kernel,
                         cudaFuncAttributeMaxDynamicSharedMemorySize, EDGE_SMEM_BYTES);

    zero_kernel<<<512, 256>>>();
    node_pre_kernel<<<(N_NODES + 31) / 32, 256, 64 * 1024>>>(
        node_feats, W_up0, W_up1, W_down, W_skip0, W_skip1, out_sc);
    edge_kernel<<<N_EDGES / 64, 256, EDGE_SMEM_BYTES>>>(
        edge_attrs, edge_feats, edge_index, Wm0, Wm1, Wm2, Wm3);
    node_post_kernel<<<(N_NODES + 31) / 32, 256>>>(W_lin0, W_lin1, out);
}